// round 1
// baseline (speedup 1.0000x reference)
#include <cuda_runtime.h>
#include <cuda_bf16.h>
#include <math.h>

// Problem dims (fixed by the reference)
constexpr int B_  = 8;
constexpr int T_  = 200;
constexpr int U_  = 50;
constexpr int D_  = 512;   // D_enc = D_dec
constexpr int J_  = 512;
constexpr int V_  = 1024;

constexpr int ME = B_ * T_;        // 1600 rows of E
constexpr int MD = B_ * U_;        // 400 rows of D
constexpr int MZ = B_ * T_ * U_;   // 80000 rows of Z / output

// Scratch (device globals: allocation-free per harness rules)
__device__ float g_E[(size_t)ME * J_];            // 3.2 MB
__device__ float g_D[(size_t)MD * J_];            // 0.8 MB
__device__ float g_Z[(size_t)MZ * J_];            // 163.8 MB

// ---------------------------------------------------------------------------
// Generic tiled fp32 GEMM:  C[M,N] = A[M,K] @ Bm[N,K]^T (+ bias[N])
// Requires: K % BK == 0, N % 4 == 0, (BM/TM)*(BN/TN) == 256 threads,
//           TN % 4 == 0, K row stride usable with float4 (K % 4 == 0).
// GUARD: clamp/guard M and N tile edges.
// ---------------------------------------------------------------------------
template <int BM, int BN, int BK, int TM, int TN, bool GUARD>
__global__ __launch_bounds__(256)
void gemm_nt_kernel(const float* __restrict__ A,
                    const float* __restrict__ Bm,
                    const float* __restrict__ bias,   // may be nullptr
                    float* __restrict__ C,
                    int M, int N, int K)
{
    // +4 pad keeps 16B alignment of each k-row while breaking store conflicts
    __shared__ float As[BK][BM + 4];
    __shared__ float Bs[BK][BN + 4];

    const int brow = blockIdx.y * BM;
    const int bcol = blockIdx.x * BN;
    const int tid  = threadIdx.x;

    const int tx = tid % (BN / TN);     // column group
    const int ty = tid / (BN / TN);     // row group

    // Loader mapping: BK=16 -> 4 float4 per row, 64 rows covered per pass
    const int lRow  = tid / 4;          // 0..63
    const int lCol4 = (tid % 4) * 4;    // 0,4,8,12
    constexpr int RSTEP = 256 / (BK / 4);   // 64

    float acc[TM][TN];
    #pragma unroll
    for (int i = 0; i < TM; ++i)
        #pragma unroll
        for (int j = 0; j < TN; ++j) acc[i][j] = 0.0f;

    float ra[TM], rb[TN];

    for (int k0 = 0; k0 < K; k0 += BK) {
        // --- load A tile (rows brow..brow+BM) ---
        #pragma unroll
        for (int r = 0; r < BM; r += RSTEP) {
            int row = brow + lRow + r;
            if (GUARD) row = min(row, M - 1);
            float4 v = *reinterpret_cast<const float4*>(
                A + (size_t)row * K + k0 + lCol4);
            As[lCol4 + 0][lRow + r] = v.x;
            As[lCol4 + 1][lRow + r] = v.y;
            As[lCol4 + 2][lRow + r] = v.z;
            As[lCol4 + 3][lRow + r] = v.w;
        }
        // --- load B tile (rows of Bm = output columns bcol..bcol+BN) ---
        #pragma unroll
        for (int r = 0; r < BN; r += RSTEP) {
            int row = bcol + lRow + r;
            if (GUARD) row = min(row, N - 1);
            float4 v = *reinterpret_cast<const float4*>(
                Bm + (size_t)row * K + k0 + lCol4);
            Bs[lCol4 + 0][lRow + r] = v.x;
            Bs[lCol4 + 1][lRow + r] = v.y;
            Bs[lCol4 + 2][lRow + r] = v.z;
            Bs[lCol4 + 3][lRow + r] = v.w;
        }
        __syncthreads();

        #pragma unroll
        for (int k = 0; k < BK; ++k) {
            #pragma unroll
            for (int i = 0; i < TM; ++i) ra[i] = As[k][ty * TM + i];
            #pragma unroll
            for (int j = 0; j < TN; ++j) rb[j] = Bs[k][tx * TN + j];
            #pragma unroll
            for (int i = 0; i < TM; ++i)
                #pragma unroll
                for (int j = 0; j < TN; ++j)
                    acc[i][j] = fmaf(ra[i], rb[j], acc[i][j]);
        }
        __syncthreads();
    }

    // --- epilogue: bias + store ---
    #pragma unroll
    for (int i = 0; i < TM; ++i) {
        const int row = brow + ty * TM + i;
        if (GUARD && row >= M) continue;
        #pragma unroll
        for (int j4 = 0; j4 < TN / 4; ++j4) {
            const int col = bcol + tx * TN + j4 * 4;
            if (GUARD && col >= N) continue;
            float4 o;
            if (bias != nullptr) {
                o.x = acc[i][j4 * 4 + 0] + bias[col + 0];
                o.y = acc[i][j4 * 4 + 1] + bias[col + 1];
                o.z = acc[i][j4 * 4 + 2] + bias[col + 2];
                o.w = acc[i][j4 * 4 + 3] + bias[col + 3];
            } else {
                o.x = acc[i][j4 * 4 + 0];
                o.y = acc[i][j4 * 4 + 1];
                o.z = acc[i][j4 * 4 + 2];
                o.w = acc[i][j4 * 4 + 3];
            }
            *reinterpret_cast<float4*>(C + (size_t)row * N + col) = o;
        }
    }
}

// ---------------------------------------------------------------------------
// Z[m, j] = tanh(E[bt(m), j] + D[b(m)*U + u(m), j]),  vectorized float4 on j
// ---------------------------------------------------------------------------
__global__ __launch_bounds__(256)
void tanh_broadcast_kernel()
{
    const int J4 = J_ / 4;                         // 128 float4 per row
    const long long total = (long long)MZ * J4;    // 10,240,000
    long long gid = (long long)blockIdx.x * blockDim.x + threadIdx.x;
    if (gid >= total) return;

    const int m  = (int)(gid / J4);
    const int jj = ((int)(gid % J4)) * 4;

    const int bt = m / U_;            // encoder row
    const int u  = m - bt * U_;
    const int b  = m / (T_ * U_);
    const int dr = b * U_ + u;        // decoder row

    const float4 e = *reinterpret_cast<const float4*>(g_E + (size_t)bt * J_ + jj);
    const float4 d = *reinterpret_cast<const float4*>(g_D + (size_t)dr * J_ + jj);

    float4 z;
    z.x = tanhf(e.x + d.x);
    z.y = tanhf(e.y + d.y);
    z.z = tanhf(e.z + d.z);
    z.w = tanhf(e.w + d.w);
    *reinterpret_cast<float4*>(g_Z + (size_t)m * J_ + jj) = z;
}

// ---------------------------------------------------------------------------
extern "C" void kernel_launch(void* const* d_in, const int* in_sizes, int n_in,
                              void* d_out, int out_size)
{
    const float* h_enc = (const float*)d_in[0];   // (1600, 512)
    const float* h_dec = (const float*)d_in[1];   // (400, 512)
    const float* W_enc = (const float*)d_in[2];   // (512, 512)
    const float* b_enc = (const float*)d_in[3];   // (512,)
    const float* W_dec = (const float*)d_in[4];   // (512, 512)
    const float* W_out = (const float*)d_in[5];   // (1024, 512)
    const float* b_out = (const float*)d_in[6];   // (1024,)
    float* out = (float*)d_out;                   // (80000, 1024)

    float* E;  cudaGetSymbolAddress((void**)&E, g_E);
    float* D;  cudaGetSymbolAddress((void**)&D, g_D);
    float* Z;  cudaGetSymbolAddress((void**)&Z, g_Z);

    // 1) E = h_enc @ W_enc^T + b_enc   (1600 x 512, K=512)
    {
        dim3 grid(J_ / 64, (ME + 63) / 64);
        gemm_nt_kernel<64, 64, 16, 4, 4, true><<<grid, 256>>>(
            h_enc, W_enc, b_enc, E, ME, J_, D_);
    }
    // 2) D = h_dec @ W_dec^T           (400 x 512, K=512)
    {
        dim3 grid(J_ / 64, (MD + 63) / 64);
        gemm_nt_kernel<64, 64, 16, 4, 4, true><<<grid, 256>>>(
            h_dec, W_dec, nullptr, D, MD, J_, D_);
    }
    // 3) Z = tanh(E broadcast+ D)      (80000 x 512)
    {
        const long long total = (long long)MZ * (J_ / 4);
        const int blocks = (int)((total + 255) / 256);
        tanh_broadcast_kernel<<<blocks, 256>>>();
    }
    // 4) out = Z @ W_out^T + b_out     (80000 x 1024, K=512) — dominant GEMM
    {
        dim3 grid(V_ / 128, MZ / 128);   // (8, 625)
        gemm_nt_kernel<128, 128, 16, 8, 8, false><<<grid, 256>>>(
            Z, W_out, b_out, out, MZ, V_, J_);
    }
}

// round 3
// speedup vs baseline: 2.7462x; 2.7462x over previous
#include <cuda_runtime.h>
#include <cstdint>
#include <math.h>

// ---------------------------------------------------------------------------
// Problem dims (fixed by the reference)
// ---------------------------------------------------------------------------
constexpr int B_  = 8;
constexpr int T_  = 200;
constexpr int U_  = 50;
constexpr int D_  = 512;   // D_enc = D_dec
constexpr int J_  = 512;
constexpr int V_  = 1024;

constexpr int ME = B_ * T_;        // 1600 rows of E
constexpr int MD = B_ * U_;        // 400 rows of D
constexpr int MZ = B_ * T_ * U_;   // 80000 rows of Z / output

// Scratch (device globals: allocation-free per harness rules)
__device__ float g_E[(size_t)ME * J_];            // 3.2 MB
__device__ float g_D[(size_t)MD * J_];            // 0.8 MB
__device__ float g_Z[(size_t)MZ * J_];            // 163.8 MB (tf32-rounded)
__device__ float g_Wr[(size_t)V_ * J_];           // 2 MB   (tf32-rounded W_out)

// ---------------------------------------------------------------------------
// Helpers
// ---------------------------------------------------------------------------
__device__ __forceinline__ uint32_t smem_to_u32(const void* p) {
    uint32_t a;
    asm("{ .reg .u64 t; cvta.to.shared.u64 t, %1; cvt.u32.u64 %0, t; }"
        : "=r"(a) : "l"(p));
    return a;
}

#define CP_ASYNC16(saddr, gaddr) \
    asm volatile("cp.async.cg.shared.global [%0], [%1], 16;" :: "r"(saddr), "l"(gaddr) : "memory")
#define CP_ASYNC_COMMIT() asm volatile("cp.async.commit_group;" ::: "memory")
#define CP_ASYNC_WAIT1()  asm volatile("cp.async.wait_group 1;" ::: "memory")
#define CP_ASYNC_WAIT0()  asm volatile("cp.async.wait_group 0;" ::: "memory")

__device__ __forceinline__ float to_tf32_rn(float x) {
    uint32_t b;
    asm("cvt.rna.tf32.f32 %0, %1;" : "=r"(b) : "f"(x));
    return __uint_as_float(b);
}

// m16n8k8 tf32 mma: D += A(16x8, row) * B(8x8, col)
__device__ __forceinline__ void mma_tf32(float* d,
                                         uint32_t a0, uint32_t a1, uint32_t a2, uint32_t a3,
                                         uint32_t b0, uint32_t b1) {
    asm volatile(
        "mma.sync.aligned.m16n8k8.row.col.f32.tf32.tf32.f32 "
        "{%0,%1,%2,%3}, {%4,%5,%6,%7}, {%8,%9}, {%0,%1,%2,%3};"
        : "+f"(d[0]), "+f"(d[1]), "+f"(d[2]), "+f"(d[3])
        : "r"(a0), "r"(a1), "r"(a2), "r"(a3), "r"(b0), "r"(b1));
}

// ---------------------------------------------------------------------------
// Small SIMT fp32 GEMM (layer 1):  C[M,N] = A[M,K] @ Bm[N,K]^T (+ bias)
// ---------------------------------------------------------------------------
template <int BM, int BN, int BK, int TM, int TN, bool GUARD>
__global__ __launch_bounds__(256)
void gemm_nt_kernel(const float* __restrict__ A,
                    const float* __restrict__ Bm,
                    const float* __restrict__ bias,
                    float* __restrict__ C,
                    int M, int N, int K)
{
    __shared__ float As[BK][BM + 4];
    __shared__ float Bs[BK][BN + 4];

    const int brow = blockIdx.y * BM;
    const int bcol = blockIdx.x * BN;
    const int tid  = threadIdx.x;
    const int tx = tid % (BN / TN);
    const int ty = tid / (BN / TN);
    const int lRow  = tid / 4;
    const int lCol4 = (tid % 4) * 4;
    constexpr int RSTEP = 256 / (BK / 4);

    float acc[TM][TN];
    #pragma unroll
    for (int i = 0; i < TM; ++i)
        #pragma unroll
        for (int j = 0; j < TN; ++j) acc[i][j] = 0.0f;

    float ra[TM], rb[TN];

    for (int k0 = 0; k0 < K; k0 += BK) {
        #pragma unroll
        for (int r = 0; r < BM; r += RSTEP) {
            int row = brow + lRow + r;
            if (GUARD) row = min(row, M - 1);
            float4 v = *reinterpret_cast<const float4*>(A + (size_t)row * K + k0 + lCol4);
            As[lCol4 + 0][lRow + r] = v.x;
            As[lCol4 + 1][lRow + r] = v.y;
            As[lCol4 + 2][lRow + r] = v.z;
            As[lCol4 + 3][lRow + r] = v.w;
        }
        #pragma unroll
        for (int r = 0; r < BN; r += RSTEP) {
            int row = bcol + lRow + r;
            if (GUARD) row = min(row, N - 1);
            float4 v = *reinterpret_cast<const float4*>(Bm + (size_t)row * K + k0 + lCol4);
            Bs[lCol4 + 0][lRow + r] = v.x;
            Bs[lCol4 + 1][lRow + r] = v.y;
            Bs[lCol4 + 2][lRow + r] = v.z;
            Bs[lCol4 + 3][lRow + r] = v.w;
        }
        __syncthreads();

        #pragma unroll
        for (int k = 0; k < BK; ++k) {
            #pragma unroll
            for (int i = 0; i < TM; ++i) ra[i] = As[k][ty * TM + i];
            #pragma unroll
            for (int j = 0; j < TN; ++j) rb[j] = Bs[k][tx * TN + j];
            #pragma unroll
            for (int i = 0; i < TM; ++i)
                #pragma unroll
                for (int j = 0; j < TN; ++j)
                    acc[i][j] = fmaf(ra[i], rb[j], acc[i][j]);
        }
        __syncthreads();
    }

    #pragma unroll
    for (int i = 0; i < TM; ++i) {
        const int row = brow + ty * TM + i;
        if (GUARD && row >= M) continue;
        #pragma unroll
        for (int j4 = 0; j4 < TN / 4; ++j4) {
            const int col = bcol + tx * TN + j4 * 4;
            if (GUARD && col >= N) continue;
            float4 o;
            o.x = acc[i][j4 * 4 + 0] + (bias ? bias[col + 0] : 0.0f);
            o.y = acc[i][j4 * 4 + 1] + (bias ? bias[col + 1] : 0.0f);
            o.z = acc[i][j4 * 4 + 2] + (bias ? bias[col + 2] : 0.0f);
            o.w = acc[i][j4 * 4 + 3] + (bias ? bias[col + 3] : 0.0f);
            *reinterpret_cast<float4*>(C + (size_t)row * N + col) = o;
        }
    }
}

// ---------------------------------------------------------------------------
// Z[m, j] = tf32_rn(tanh(E[bt, j] + D[b*U+u, j]))
// ---------------------------------------------------------------------------
__global__ __launch_bounds__(256)
void tanh_broadcast_kernel()
{
    const int J4 = J_ / 4;
    const long long total = (long long)MZ * J4;
    long long gid = (long long)blockIdx.x * blockDim.x + threadIdx.x;
    if (gid >= total) return;

    const int m  = (int)(gid / J4);
    const int jj = ((int)(gid % J4)) * 4;

    const int bt = m / U_;
    const int u  = m - bt * U_;
    const int b  = m / (T_ * U_);
    const int dr = b * U_ + u;

    const float4 e = *reinterpret_cast<const float4*>(g_E + (size_t)bt * J_ + jj);
    const float4 d = *reinterpret_cast<const float4*>(g_D + (size_t)dr * J_ + jj);

    float4 z;
    z.x = to_tf32_rn(tanhf(e.x + d.x));
    z.y = to_tf32_rn(tanhf(e.y + d.y));
    z.z = to_tf32_rn(tanhf(e.z + d.z));
    z.w = to_tf32_rn(tanhf(e.w + d.w));
    *reinterpret_cast<float4*>(g_Z + (size_t)m * J_ + jj) = z;
}

// W_out -> tf32-rounded copy
__global__ __launch_bounds__(256)
void round_wout_kernel(const float* __restrict__ W)
{
    int i = blockIdx.x * 256 + threadIdx.x;
    const int total4 = V_ * J_ / 4;
    if (i >= total4) return;
    float4 v = *reinterpret_cast<const float4*>(W + (size_t)i * 4);
    v.x = to_tf32_rn(v.x); v.y = to_tf32_rn(v.y);
    v.z = to_tf32_rn(v.z); v.w = to_tf32_rn(v.w);
    *reinterpret_cast<float4*>(g_Wr + (size_t)i * 4) = v;
}

// ---------------------------------------------------------------------------
// Main GEMM on mma.sync tf32:
//   out[80000, 1024] = Z[80000, 512] @ Wr[1024, 512]^T + b_out
// BM=128, BN=256, BK=32; 512 threads (16 warps, 4x4), warp tile 32x64.
// 2-stage cp.async pipeline. Smem tiles row-major [row][36] (144B rows).
// ---------------------------------------------------------------------------
constexpr int TC_BM = 128;
constexpr int TC_BN = 256;
constexpr int TC_BK = 32;
constexpr int TC_NKB = J_ / TC_BK;     // 16 K-blocks
constexpr int TC_THREADS = 512;

constexpr int ROWF = 36;               // floats per smem row (32 + 4 pad)
constexpr int A_BYTES = TC_BM * ROWF * 4;   // 18432
constexpr int B_BYTES = TC_BN * ROWF * 4;   // 36864
constexpr int STAGE_BYTES = A_BYTES + B_BYTES;   // 55296
constexpr int SM_BIAS  = 2 * STAGE_BYTES;        // 110592
constexpr int SM_TOTAL = SM_BIAS + TC_BN * 4;    // 111616

__global__ __launch_bounds__(TC_THREADS, 1)
void joint_out_mma(const float* __restrict__ Z,
                   const float* __restrict__ Wr,
                   const float* __restrict__ bias,
                   float* __restrict__ out)
{
    extern __shared__ char smem[];
    const uint32_t smem_base = smem_to_u32(smem);

    const int tid  = threadIdx.x;
    const int lane = tid & 31;
    const int wid  = tid >> 5;
    const int wm   = wid & 3;        // warp row (M)
    const int wn   = wid >> 2;       // warp col (N)

    const int brow = blockIdx.y * TC_BM;
    const int bcol = blockIdx.x * TC_BN;

    const float* Abase = Z  + (size_t)brow * J_;
    const float* Bbase = Wr + (size_t)bcol * J_;

    // stage bias
    float* sb = reinterpret_cast<float*>(smem + SM_BIAS);
    if (tid < TC_BN) sb[tid] = bias[bcol + tid];

    // --- loader: 16B granules. A: 1024 granules, B: 2048 granules ---
    auto load_stage = [&](int kt, int s) {
        const uint32_t sba = smem_base + s * STAGE_BYTES;
        const float* ag = Abase + kt * TC_BK;
        #pragma unroll
        for (int i = 0; i < 2; ++i) {
            int g = tid + i * TC_THREADS;
            int row = g >> 3, gc = g & 7;
            CP_ASYNC16(sba + row * (ROWF * 4) + gc * 16,
                       ag + (size_t)row * J_ + gc * 4);
        }
        const uint32_t sbb = sba + A_BYTES;
        const float* bg = Bbase + kt * TC_BK;
        #pragma unroll
        for (int i = 0; i < 4; ++i) {
            int g = tid + i * TC_THREADS;
            int row = g >> 3, gc = g & 7;
            CP_ASYNC16(sbb + row * (ROWF * 4) + gc * 16,
                       bg + (size_t)row * J_ + gc * 4);
        }
        CP_ASYNC_COMMIT();
    };

    float acc[2][8][4];
    #pragma unroll
    for (int i = 0; i < 2; ++i)
        #pragma unroll
        for (int j = 0; j < 8; ++j)
            #pragma unroll
            for (int r = 0; r < 4; ++r) acc[i][j][r] = 0.0f;

    load_stage(0, 0);

    const int mA = wm * 32 + (lane >> 2);   // A row for fragment (add i*16, +8)
    const int nB = wn * 64 + (lane >> 2);   // B row for fragment (add j*8)
    const int kq = lane & 3;

    #pragma unroll 1
    for (int kt = 0; kt < TC_NKB; ++kt) {
        const int s = kt & 1;
        if (kt + 1 < TC_NKB) {
            load_stage(kt + 1, s ^ 1);
            CP_ASYNC_WAIT1();
        } else {
            CP_ASYNC_WAIT0();
        }
        __syncthreads();

        const float* As = reinterpret_cast<const float*>(smem + s * STAGE_BYTES);
        const float* Bs = reinterpret_cast<const float*>(smem + s * STAGE_BYTES + A_BYTES);

        #pragma unroll
        for (int ks = 0; ks < 4; ++ks) {
            const int kb = ks * 8 + kq;
            uint32_t a[2][4];
            #pragma unroll
            for (int i = 0; i < 2; ++i) {
                const float* ap = As + (mA + i * 16) * ROWF + kb;
                a[i][0] = __float_as_uint(ap[0]);
                a[i][1] = __float_as_uint(ap[8 * ROWF]);
                a[i][2] = __float_as_uint(ap[4]);
                a[i][3] = __float_as_uint(ap[8 * ROWF + 4]);
            }
            uint32_t b[8][2];
            #pragma unroll
            for (int j = 0; j < 8; ++j) {
                const float* bp = Bs + (nB + j * 8) * ROWF + kb;
                b[j][0] = __float_as_uint(bp[0]);
                b[j][1] = __float_as_uint(bp[4]);
            }
            #pragma unroll
            for (int i = 0; i < 2; ++i)
                #pragma unroll
                for (int j = 0; j < 8; ++j)
                    mma_tf32(acc[i][j], a[i][0], a[i][1], a[i][2], a[i][3],
                             b[j][0], b[j][1]);
        }
        __syncthreads();   // protect stage s from being overwritten next iter
    }

    // --- epilogue: bias + direct global stores (float2 per fragment row) ---
    #pragma unroll
    for (int i = 0; i < 2; ++i) {
        const int r = brow + wm * 32 + i * 16 + (lane >> 2);
        #pragma unroll
        for (int j = 0; j < 8; ++j) {
            const int cl = wn * 64 + j * 8 + 2 * (lane & 3);   // local col in [0,256)
            const float bx = sb[cl], by = sb[cl + 1];
            float2 v0 = { acc[i][j][0] + bx, acc[i][j][1] + by };
            float2 v1 = { acc[i][j][2] + bx, acc[i][j][3] + by };
            *reinterpret_cast<float2*>(out + (size_t)r * V_ + bcol + cl) = v0;
            *reinterpret_cast<float2*>(out + (size_t)(r + 8) * V_ + bcol + cl) = v1;
        }
    }
}

// ---------------------------------------------------------------------------
extern "C" void kernel_launch(void* const* d_in, const int* in_sizes, int n_in,
                              void* d_out, int out_size)
{
    const float* h_enc = (const float*)d_in[0];   // (1600, 512)
    const float* h_dec = (const float*)d_in[1];   // (400, 512)
    const float* W_enc = (const float*)d_in[2];   // (512, 512)
    const float* b_enc = (const float*)d_in[3];   // (512,)
    const float* W_dec = (const float*)d_in[4];   // (512, 512)
    const float* W_out = (const float*)d_in[5];   // (1024, 512)
    const float* b_out = (const float*)d_in[6];   // (1024,)
    float* out = (float*)d_out;                   // (80000, 1024)

    float* E;  cudaGetSymbolAddress((void**)&E, g_E);
    float* D;  cudaGetSymbolAddress((void**)&D, g_D);
    float* Z;  cudaGetSymbolAddress((void**)&Z, g_Z);
    float* Wr; cudaGetSymbolAddress((void**)&Wr, g_Wr);

    static bool attr_set = false;
    if (!attr_set) {
        cudaFuncSetAttribute(joint_out_mma,
                             cudaFuncAttributeMaxDynamicSharedMemorySize, SM_TOTAL);
        attr_set = true;
    }

    // 1) E = h_enc @ W_enc^T + b_enc   (fp32)
    {
        dim3 grid(J_ / 64, (ME + 63) / 64);
        gemm_nt_kernel<64, 64, 16, 4, 4, true><<<grid, 256>>>(
            h_enc, W_enc, b_enc, E, ME, J_, D_);
    }
    // 2) D = h_dec @ W_dec^T           (fp32)
    {
        dim3 grid(J_ / 64, (MD + 63) / 64);
        gemm_nt_kernel<64, 64, 16, 4, 4, true><<<grid, 256>>>(
            h_dec, W_dec, nullptr, D, MD, J_, D_);
    }
    // 3) tf32-round W_out
    {
        const int total4 = V_ * J_ / 4;
        round_wout_kernel<<<(total4 + 255) / 256, 256>>>(W_out);
    }
    // 4) Z = tf32_rn(tanh(E + D))
    {
        const long long total = (long long)MZ * (J_ / 4);
        tanh_broadcast_kernel<<<(int)((total + 255) / 256), 256>>>();
    }
    // 5) out = Z @ Wr^T + b_out  on mma.sync tf32
    {
        dim3 grid(V_ / TC_BN, MZ / TC_BM);   // (4, 625)
        joint_out_mma<<<grid, TC_THREADS, SM_TOTAL>>>(Z, Wr, b_out, out);
    }
}

// round 4
// speedup vs baseline: 4.4066x; 1.6047x over previous
#include <cuda_runtime.h>
#include <cuda_fp16.h>
#include <cstdint>
#include <math.h>

// ---------------------------------------------------------------------------
// Problem dims (fixed by the reference)
// ---------------------------------------------------------------------------
constexpr int B_  = 8;
constexpr int T_  = 200;
constexpr int U_  = 50;
constexpr int D_  = 512;   // D_enc = D_dec
constexpr int J_  = 512;
constexpr int V_  = 1024;

constexpr int ME = B_ * T_;        // 1600 rows of E
constexpr int MD = B_ * U_;        // 400 rows of D
constexpr int MZ = B_ * T_ * U_;   // 80000 rows of Z / output

// Scratch (device globals: allocation-free per harness rules)
__device__ float  g_E[(size_t)ME * J_];            // 3.2 MB
__device__ float  g_D[(size_t)MD * J_];            // 0.8 MB
__device__ __half g_Zh[(size_t)MZ * J_];           // 81.9 MB (fp16 Z)
__device__ __half g_Wh[(size_t)V_ * J_];           // 1 MB   (fp16 W_out)

// ---------------------------------------------------------------------------
// Helpers
// ---------------------------------------------------------------------------
__device__ __forceinline__ uint32_t smem_to_u32(const void* p) {
    uint32_t a;
    asm("{ .reg .u64 t; cvta.to.shared.u64 t, %1; cvt.u32.u64 %0, t; }"
        : "=r"(a) : "l"(p));
    return a;
}

#define CP_ASYNC16(saddr, gaddr) \
    asm volatile("cp.async.cg.shared.global [%0], [%1], 16;" :: "r"(saddr), "l"(gaddr) : "memory")
#define CP_ASYNC_COMMIT() asm volatile("cp.async.commit_group;" ::: "memory")
#define CP_ASYNC_WAIT1()  asm volatile("cp.async.wait_group 1;" ::: "memory")
#define CP_ASYNC_WAIT0()  asm volatile("cp.async.wait_group 0;" ::: "memory")

// m16n8k16 fp16 mma, fp32 accumulate
__device__ __forceinline__ void mma_f16(float* d,
                                        uint32_t a0, uint32_t a1, uint32_t a2, uint32_t a3,
                                        uint32_t b0, uint32_t b1) {
    asm volatile(
        "mma.sync.aligned.m16n8k16.row.col.f32.f16.f16.f32 "
        "{%0,%1,%2,%3}, {%4,%5,%6,%7}, {%8,%9}, {%0,%1,%2,%3};"
        : "+f"(d[0]), "+f"(d[1]), "+f"(d[2]), "+f"(d[3])
        : "r"(a0), "r"(a1), "r"(a2), "r"(a3), "r"(b0), "r"(b1));
}

// ---------------------------------------------------------------------------
// Small SIMT fp32 GEMM (layer 1):  C[M,N] = A[M,K] @ Bm[N,K]^T (+ bias)
// ---------------------------------------------------------------------------
template <int BM, int BN, int BK, int TM, int TN, bool GUARD>
__global__ __launch_bounds__(256)
void gemm_nt_kernel(const float* __restrict__ A,
                    const float* __restrict__ Bm,
                    const float* __restrict__ bias,
                    float* __restrict__ C,
                    int M, int N, int K)
{
    __shared__ float As[BK][BM + 4];
    __shared__ float Bs[BK][BN + 4];

    const int brow = blockIdx.y * BM;
    const int bcol = blockIdx.x * BN;
    const int tid  = threadIdx.x;
    const int tx = tid % (BN / TN);
    const int ty = tid / (BN / TN);
    const int lRow  = tid / 4;
    const int lCol4 = (tid % 4) * 4;
    constexpr int RSTEP = 256 / (BK / 4);

    float acc[TM][TN];
    #pragma unroll
    for (int i = 0; i < TM; ++i)
        #pragma unroll
        for (int j = 0; j < TN; ++j) acc[i][j] = 0.0f;

    float ra[TM], rb[TN];

    for (int k0 = 0; k0 < K; k0 += BK) {
        #pragma unroll
        for (int r = 0; r < BM; r += RSTEP) {
            int row = brow + lRow + r;
            if (GUARD) row = min(row, M - 1);
            float4 v = *reinterpret_cast<const float4*>(A + (size_t)row * K + k0 + lCol4);
            As[lCol4 + 0][lRow + r] = v.x;
            As[lCol4 + 1][lRow + r] = v.y;
            As[lCol4 + 2][lRow + r] = v.z;
            As[lCol4 + 3][lRow + r] = v.w;
        }
        #pragma unroll
        for (int r = 0; r < BN; r += RSTEP) {
            int row = bcol + lRow + r;
            if (GUARD) row = min(row, N - 1);
            float4 v = *reinterpret_cast<const float4*>(Bm + (size_t)row * K + k0 + lCol4);
            Bs[lCol4 + 0][lRow + r] = v.x;
            Bs[lCol4 + 1][lRow + r] = v.y;
            Bs[lCol4 + 2][lRow + r] = v.z;
            Bs[lCol4 + 3][lRow + r] = v.w;
        }
        __syncthreads();

        #pragma unroll
        for (int k = 0; k < BK; ++k) {
            #pragma unroll
            for (int i = 0; i < TM; ++i) ra[i] = As[k][ty * TM + i];
            #pragma unroll
            for (int j = 0; j < TN; ++j) rb[j] = Bs[k][tx * TN + j];
            #pragma unroll
            for (int i = 0; i < TM; ++i)
                #pragma unroll
                for (int j = 0; j < TN; ++j)
                    acc[i][j] = fmaf(ra[i], rb[j], acc[i][j]);
        }
        __syncthreads();
    }

    #pragma unroll
    for (int i = 0; i < TM; ++i) {
        const int row = brow + ty * TM + i;
        if (GUARD && row >= M) continue;
        #pragma unroll
        for (int j4 = 0; j4 < TN / 4; ++j4) {
            const int col = bcol + tx * TN + j4 * 4;
            if (GUARD && col >= N) continue;
            float4 o;
            o.x = acc[i][j4 * 4 + 0] + (bias ? bias[col + 0] : 0.0f);
            o.y = acc[i][j4 * 4 + 1] + (bias ? bias[col + 1] : 0.0f);
            o.z = acc[i][j4 * 4 + 2] + (bias ? bias[col + 2] : 0.0f);
            o.w = acc[i][j4 * 4 + 3] + (bias ? bias[col + 3] : 0.0f);
            *reinterpret_cast<float4*>(C + (size_t)row * N + col) = o;
        }
    }
}

// ---------------------------------------------------------------------------
// Zh[m, j] = half(tanh(E[bt, j] + D[b*U+u, j]))
// ---------------------------------------------------------------------------
__global__ __launch_bounds__(256)
void tanh_broadcast_kernel()
{
    const int J4 = J_ / 4;
    const long long total = (long long)MZ * J4;
    long long gid = (long long)blockIdx.x * blockDim.x + threadIdx.x;
    if (gid >= total) return;

    const int m  = (int)(gid / J4);
    const int jj = ((int)(gid % J4)) * 4;

    const int bt = m / U_;
    const int u  = m - bt * U_;
    const int b  = m / (T_ * U_);
    const int dr = b * U_ + u;

    const float4 e = *reinterpret_cast<const float4*>(g_E + (size_t)bt * J_ + jj);
    const float4 d = *reinterpret_cast<const float4*>(g_D + (size_t)dr * J_ + jj);

    __half2 h01 = __floats2half2_rn(tanhf(e.x + d.x), tanhf(e.y + d.y));
    __half2 h23 = __floats2half2_rn(tanhf(e.z + d.z), tanhf(e.w + d.w));
    uint2 st;
    st.x = *reinterpret_cast<uint32_t*>(&h01);
    st.y = *reinterpret_cast<uint32_t*>(&h23);
    *reinterpret_cast<uint2*>(g_Zh + (size_t)m * J_ + jj) = st;
}

// W_out -> fp16 copy
__global__ __launch_bounds__(256)
void round_wout_kernel(const float* __restrict__ W)
{
    int i = blockIdx.x * 256 + threadIdx.x;   // float4 granules
    const int total4 = V_ * J_ / 4;
    if (i >= total4) return;
    float4 v = *reinterpret_cast<const float4*>(W + (size_t)i * 4);
    __half2 h01 = __floats2half2_rn(v.x, v.y);
    __half2 h23 = __floats2half2_rn(v.z, v.w);
    uint2 st;
    st.x = *reinterpret_cast<uint32_t*>(&h01);
    st.y = *reinterpret_cast<uint32_t*>(&h23);
    *reinterpret_cast<uint2*>(g_Wh + (size_t)i * 4) = st;
}

// ---------------------------------------------------------------------------
// Main GEMM on mma.sync fp16 (fp32 accum):
//   out[80000, 1024] = Zh[80000, 512] @ Wh[1024, 512]^T + b_out
// BM=128, BN=256, BK=64 halves; 512 threads (16 warps, 4x4), warp tile 32x64.
// 2-stage cp.async pipeline. Smem rows: 72 halves (144 B) -> fragment LDS.32
// accesses map to banks 4r+q = 0..31, conflict-free.
// ---------------------------------------------------------------------------
constexpr int TC_BM = 128;
constexpr int TC_BN = 256;
constexpr int TC_BK = 64;              // halves per K-block (128 B rows)
constexpr int TC_NKB = J_ / TC_BK;     // 8 K-blocks
constexpr int TC_THREADS = 512;

constexpr int ROWH = 72;               // halves per smem row (64 + 8 pad)
constexpr int ROWB = ROWH * 2;         // 144 bytes
constexpr int A_BYTES = TC_BM * ROWB;            // 18432
constexpr int B_BYTES = TC_BN * ROWB;            // 36864
constexpr int STAGE_BYTES = A_BYTES + B_BYTES;   // 55296
constexpr int SM_BIAS  = 2 * STAGE_BYTES;        // 110592
constexpr int SM_TOTAL = SM_BIAS + TC_BN * 4;    // 111616

__global__ __launch_bounds__(TC_THREADS, 1)
void joint_out_mma(const __half* __restrict__ Z,
                   const __half* __restrict__ Wh,
                   const float* __restrict__ bias,
                   float* __restrict__ out)
{
    extern __shared__ char smem[];
    const uint32_t smem_base = smem_to_u32(smem);

    const int tid  = threadIdx.x;
    const int lane = tid & 31;
    const int wid  = tid >> 5;
    const int wm   = wid & 3;        // warp row (M)
    const int wn   = wid >> 2;       // warp col (N)

    const int brow = blockIdx.y * TC_BM;
    const int bcol = blockIdx.x * TC_BN;

    const __half* Abase = Z  + (size_t)brow * J_;
    const __half* Bbase = Wh + (size_t)bcol * J_;

    // stage bias
    float* sb = reinterpret_cast<float*>(smem + SM_BIAS);
    if (tid < TC_BN) sb[tid] = bias[bcol + tid];

    // --- loader: 16B granules (8 halves). 8 granules per 128B row ---
    auto load_stage = [&](int kt, int s) {
        const uint32_t sba = smem_base + s * STAGE_BYTES;
        const __half* ag = Abase + kt * TC_BK;
        #pragma unroll
        for (int i = 0; i < 2; ++i) {              // A: 128 rows * 8 = 1024 granules
            int g = tid + i * TC_THREADS;
            int row = g >> 3, gc = g & 7;
            CP_ASYNC16(sba + row * ROWB + gc * 16,
                       ag + (size_t)row * J_ + gc * 8);
        }
        const uint32_t sbb = sba + A_BYTES;
        const __half* bg = Bbase + kt * TC_BK;
        #pragma unroll
        for (int i = 0; i < 4; ++i) {              // B: 256 rows * 8 = 2048 granules
            int g = tid + i * TC_THREADS;
            int row = g >> 3, gc = g & 7;
            CP_ASYNC16(sbb + row * ROWB + gc * 16,
                       bg + (size_t)row * J_ + gc * 8);
        }
        CP_ASYNC_COMMIT();
    };

    float acc[2][8][4];
    #pragma unroll
    for (int i = 0; i < 2; ++i)
        #pragma unroll
        for (int j = 0; j < 8; ++j)
            #pragma unroll
            for (int r = 0; r < 4; ++r) acc[i][j][r] = 0.0f;

    load_stage(0, 0);

    const int mA = wm * 32 + (lane >> 2);   // A row base (add i*16, +8)
    const int nB = wn * 64 + (lane >> 2);   // B row base (add j*8)
    const int kq = lane & 3;

    #pragma unroll 1
    for (int kt = 0; kt < TC_NKB; ++kt) {
        const int s = kt & 1;
        if (kt + 1 < TC_NKB) {
            load_stage(kt + 1, s ^ 1);
            CP_ASYNC_WAIT1();
        } else {
            CP_ASYNC_WAIT0();
        }
        __syncthreads();

        const __half* As = reinterpret_cast<const __half*>(smem + s * STAGE_BYTES);
        const __half* Bs = reinterpret_cast<const __half*>(smem + s * STAGE_BYTES + A_BYTES);

        #pragma unroll
        for (int ks = 0; ks < 4; ++ks) {           // 4 x k16 slices
            const int kb = ks * 16 + 2 * kq;       // half col of low k-pair
            uint32_t a[2][4];
            #pragma unroll
            for (int i = 0; i < 2; ++i) {
                const __half* ap = As + (size_t)(mA + i * 16) * ROWH + kb;
                a[i][0] = *reinterpret_cast<const uint32_t*>(ap);
                a[i][1] = *reinterpret_cast<const uint32_t*>(ap + 8 * ROWH);
                a[i][2] = *reinterpret_cast<const uint32_t*>(ap + 8);
                a[i][3] = *reinterpret_cast<const uint32_t*>(ap + 8 * ROWH + 8);
            }
            uint32_t b[8][2];
            #pragma unroll
            for (int j = 0; j < 8; ++j) {
                const __half* bp = Bs + (size_t)(nB + j * 8) * ROWH + kb;
                b[j][0] = *reinterpret_cast<const uint32_t*>(bp);
                b[j][1] = *reinterpret_cast<const uint32_t*>(bp + 8);
            }
            #pragma unroll
            for (int i = 0; i < 2; ++i)
                #pragma unroll
                for (int j = 0; j < 8; ++j)
                    mma_f16(acc[i][j], a[i][0], a[i][1], a[i][2], a[i][3],
                            b[j][0], b[j][1]);
        }
        __syncthreads();   // protect stage s from next iteration's loads
    }

    // --- epilogue: bias + direct global stores ---
    #pragma unroll
    for (int i = 0; i < 2; ++i) {
        const int r = brow + wm * 32 + i * 16 + (lane >> 2);
        #pragma unroll
        for (int j = 0; j < 8; ++j) {
            const int cl = wn * 64 + j * 8 + 2 * (lane & 3);
            const float bx = sb[cl], by = sb[cl + 1];
            float2 v0 = { acc[i][j][0] + bx, acc[i][j][1] + by };
            float2 v1 = { acc[i][j][2] + bx, acc[i][j][3] + by };
            *reinterpret_cast<float2*>(out + (size_t)r * V_ + bcol + cl) = v0;
            *reinterpret_cast<float2*>(out + (size_t)(r + 8) * V_ + bcol + cl) = v1;
        }
    }
}

// ---------------------------------------------------------------------------
extern "C" void kernel_launch(void* const* d_in, const int* in_sizes, int n_in,
                              void* d_out, int out_size)
{
    const float* h_enc = (const float*)d_in[0];   // (1600, 512)
    const float* h_dec = (const float*)d_in[1];   // (400, 512)
    const float* W_enc = (const float*)d_in[2];   // (512, 512)
    const float* b_enc = (const float*)d_in[3];   // (512,)
    const float* W_dec = (const float*)d_in[4];   // (512, 512)
    const float* W_out = (const float*)d_in[5];   // (1024, 512)
    const float* b_out = (const float*)d_in[6];   // (1024,)
    float* out = (float*)d_out;                   // (80000, 1024)

    float*  E;  cudaGetSymbolAddress((void**)&E,  g_E);
    float*  D;  cudaGetSymbolAddress((void**)&D,  g_D);
    __half* Zh; cudaGetSymbolAddress((void**)&Zh, g_Zh);
    __half* Wh; cudaGetSymbolAddress((void**)&Wh, g_Wh);

    static bool attr_set = false;
    if (!attr_set) {
        cudaFuncSetAttribute(joint_out_mma,
                             cudaFuncAttributeMaxDynamicSharedMemorySize, SM_TOTAL);
        attr_set = true;
    }

    // 1) E = h_enc @ W_enc^T + b_enc   (fp32)
    {
        dim3 grid(J_ / 64, (ME + 63) / 64);
        gemm_nt_kernel<64, 64, 16, 4, 4, true><<<grid, 256>>>(
            h_enc, W_enc, b_enc, E, ME, J_, D_);
    }
    // 2) D = h_dec @ W_dec^T           (fp32)
    {
        dim3 grid(J_ / 64, (MD + 63) / 64);
        gemm_nt_kernel<64, 64, 16, 4, 4, true><<<grid, 256>>>(
            h_dec, W_dec, nullptr, D, MD, J_, D_);
    }
    // 3) W_out -> fp16
    {
        const int total4 = V_ * J_ / 4;
        round_wout_kernel<<<(total4 + 255) / 256, 256>>>(W_out);
    }
    // 4) Zh = fp16(tanh(E + D))
    {
        const long long total = (long long)MZ * (J_ / 4);
        tanh_broadcast_kernel<<<(int)((total + 255) / 256), 256>>>();
    }
    // 5) out = Zh @ Wh^T + b_out  on mma.sync fp16
    {
        dim3 grid(V_ / TC_BN, MZ / TC_BM);   // (4, 625)
        joint_out_mma<<<grid, TC_THREADS, SM_TOTAL>>>(Zh, Wh, b_out, out);
    }
}

// round 6
// speedup vs baseline: 4.9308x; 1.1190x over previous
#include <cuda_runtime.h>
#include <cuda_fp16.h>
#include <cstdint>
#include <math.h>

// ---------------------------------------------------------------------------
// Problem dims (fixed by the reference)
// ---------------------------------------------------------------------------
constexpr int B_  = 8;
constexpr int T_  = 200;
constexpr int U_  = 50;
constexpr int D_  = 512;   // D_enc = D_dec
constexpr int J_  = 512;
constexpr int V_  = 1024;

constexpr int ME = B_ * T_;        // 1600 rows of E
constexpr int MD = B_ * U_;        // 400 rows of D
constexpr int MZ = B_ * T_ * U_;   // 80000 rows of Z / output

// Scratch (device globals: allocation-free per harness rules)
__device__ float  g_E[(size_t)ME * J_];            // 3.2 MB
__device__ float  g_D[(size_t)MD * J_];            // 0.8 MB
__device__ __half g_Zh[(size_t)MZ * J_];           // 81.9 MB (fp16 Z)
__device__ __half g_Wh[(size_t)V_ * J_];           // 1 MB   (fp16 W_out)

// ---------------------------------------------------------------------------
// Helpers
// ---------------------------------------------------------------------------
__device__ __forceinline__ uint32_t smem_to_u32(const void* p) {
    uint32_t a;
    asm("{ .reg .u64 t; cvta.to.shared.u64 t, %1; cvt.u32.u64 %0, t; }"
        : "=r"(a) : "l"(p));
    return a;
}

#define CP_ASYNC16(saddr, gaddr) \
    asm volatile("cp.async.cg.shared.global [%0], [%1], 16;" :: "r"(saddr), "l"(gaddr) : "memory")
#define CP_ASYNC_COMMIT() asm volatile("cp.async.commit_group;" ::: "memory")

__device__ __forceinline__ float tanh_fast(float x) {
    float y;
    asm("tanh.approx.f32 %0, %1;" : "=f"(y) : "f"(x));
    return y;
}

// m16n8k16 fp16 mma, fp32 accumulate
__device__ __forceinline__ void mma_f16(float* d,
                                        uint32_t a0, uint32_t a1, uint32_t a2, uint32_t a3,
                                        uint32_t b0, uint32_t b1) {
    asm volatile(
        "mma.sync.aligned.m16n8k16.row.col.f32.f16.f16.f32 "
        "{%0,%1,%2,%3}, {%4,%5,%6,%7}, {%8,%9}, {%0,%1,%2,%3};"
        : "+f"(d[0]), "+f"(d[1]), "+f"(d[2]), "+f"(d[3])
        : "r"(a0), "r"(a1), "r"(a2), "r"(a3), "r"(b0), "r"(b1));
}

// ---------------------------------------------------------------------------
// SIMT fp32 GEMM device body (layer 1):  C[M,N] = A[M,K] @ Bm[N,K]^T (+ bias)
// 256 threads, BM=BN=64, BK=16, TM=TN=4, edge rows clamped.
// ---------------------------------------------------------------------------
__device__ void gemm_nt_dev(const float* __restrict__ A,
                            const float* __restrict__ Bm,
                            const float* __restrict__ bias,
                            float* __restrict__ C,
                            int M, int N, int K, int bx, int by)
{
    constexpr int BM = 64, BN = 64, BK = 16, TM = 4, TN = 4;
    __shared__ float As[BK][BM + 4];
    __shared__ float Bs[BK][BN + 4];

    const int brow = by * BM;
    const int bcol = bx * BN;
    const int tid  = threadIdx.x;
    const int tx = tid % (BN / TN);
    const int ty = tid / (BN / TN);
    const int lRow  = tid / 4;
    const int lCol4 = (tid % 4) * 4;

    float acc[TM][TN];
    #pragma unroll
    for (int i = 0; i < TM; ++i)
        #pragma unroll
        for (int j = 0; j < TN; ++j) acc[i][j] = 0.0f;

    float ra[TM], rb[TN];

    for (int k0 = 0; k0 < K; k0 += BK) {
        {
            int row = min(brow + lRow, M - 1);
            float4 v = *reinterpret_cast<const float4*>(A + (size_t)row * K + k0 + lCol4);
            As[lCol4 + 0][lRow] = v.x;
            As[lCol4 + 1][lRow] = v.y;
            As[lCol4 + 2][lRow] = v.z;
            As[lCol4 + 3][lRow] = v.w;
        }
        {
            int row = min(bcol + lRow, N - 1);
            float4 v = *reinterpret_cast<const float4*>(Bm + (size_t)row * K + k0 + lCol4);
            Bs[lCol4 + 0][lRow] = v.x;
            Bs[lCol4 + 1][lRow] = v.y;
            Bs[lCol4 + 2][lRow] = v.z;
            Bs[lCol4 + 3][lRow] = v.w;
        }
        __syncthreads();

        #pragma unroll
        for (int k = 0; k < BK; ++k) {
            #pragma unroll
            for (int i = 0; i < TM; ++i) ra[i] = As[k][ty * TM + i];
            #pragma unroll
            for (int j = 0; j < TN; ++j) rb[j] = Bs[k][tx * TN + j];
            #pragma unroll
            for (int i = 0; i < TM; ++i)
                #pragma unroll
                for (int j = 0; j < TN; ++j)
                    acc[i][j] = fmaf(ra[i], rb[j], acc[i][j]);
        }
        __syncthreads();
    }

    #pragma unroll
    for (int i = 0; i < TM; ++i) {
        const int row = brow + ty * TM + i;
        if (row >= M) continue;
        #pragma unroll
        for (int j4 = 0; j4 < TN / 4; ++j4) {
            const int col = bcol + tx * TN + j4 * 4;
            float4 o;
            o.x = acc[i][j4 * 4 + 0] + (bias ? bias[col + 0] : 0.0f);
            o.y = acc[i][j4 * 4 + 1] + (bias ? bias[col + 1] : 0.0f);
            o.z = acc[i][j4 * 4 + 2] + (bias ? bias[col + 2] : 0.0f);
            o.w = acc[i][j4 * 4 + 3] + (bias ? bias[col + 3] : 0.0f);
            *reinterpret_cast<float4*>(C + (size_t)row * N + col) = o;
        }
    }
}

// ---------------------------------------------------------------------------
// Fused prep: z=0 -> E gemm; z=1 -> D gemm; z=2 -> W_out -> fp16 conversion
// grid (8, 25, 3), 256 threads
// ---------------------------------------------------------------------------
constexpr int D_GRID_Y = (MD + 63) / 64;   // 7

__global__ __launch_bounds__(256)
void prep_kernel(const float* __restrict__ h_enc, const float* __restrict__ W_enc,
                 const float* __restrict__ b_enc,
                 const float* __restrict__ h_dec, const float* __restrict__ W_dec,
                 const float* __restrict__ W_out)
{
    const int z = blockIdx.z;
    if (z == 0) {
        gemm_nt_dev(h_enc, W_enc, b_enc, g_E, ME, J_, D_, blockIdx.x, blockIdx.y);
    } else if (z == 1) {
        if (blockIdx.y < D_GRID_Y)
            gemm_nt_dev(h_dec, W_dec, nullptr, g_D, MD, J_, D_, blockIdx.x, blockIdx.y);
    } else {
        // W_out (1024x512 fp32) -> g_Wh, 8 floats per iteration
        const int nthr = gridDim.x * gridDim.y * 256;   // 51200
        int t = (blockIdx.y * gridDim.x + blockIdx.x) * 256 + threadIdx.x;
        const int total8 = V_ * J_ / 8;                 // 65536
        for (int i = t; i < total8; i += nthr) {
            float4 v0 = *reinterpret_cast<const float4*>(W_out + (size_t)i * 8);
            float4 v1 = *reinterpret_cast<const float4*>(W_out + (size_t)i * 8 + 4);
            __half2 h0 = __floats2half2_rn(v0.x, v0.y);
            __half2 h1 = __floats2half2_rn(v0.z, v0.w);
            __half2 h2 = __floats2half2_rn(v1.x, v1.y);
            __half2 h3 = __floats2half2_rn(v1.z, v1.w);
            uint4 st;
            st.x = *reinterpret_cast<uint32_t*>(&h0);
            st.y = *reinterpret_cast<uint32_t*>(&h1);
            st.z = *reinterpret_cast<uint32_t*>(&h2);
            st.w = *reinterpret_cast<uint32_t*>(&h3);
            *reinterpret_cast<uint4*>(g_Wh + (size_t)i * 8) = st;
        }
    }
}

// ---------------------------------------------------------------------------
// tanh pass: one block per encoder row bt (1600 blocks).
// Zh[bt*U + u, j] = half(tanh_approx(E[bt, j] + D[b*U + u, j]))
// No per-element division; E row cached in smem; 8 halves per store.
// ---------------------------------------------------------------------------
__global__ __launch_bounds__(256)
void tanh_broadcast_kernel()
{
    const int bt = blockIdx.x;                 // 0..1599
    const int b  = bt / T_;                    // one div per block

    __shared__ float se[J_];
    {
        const float* erow = g_E + (size_t)bt * J_;
        for (int i = threadIdx.x; i < J_ / 4; i += 256)
            *reinterpret_cast<float4*>(se + i * 4) =
                *reinterpret_cast<const float4*>(erow + i * 4);
    }
    __syncthreads();

    const float* dbase = g_D + (size_t)b * U_ * J_;
    __half* zbase = g_Zh + (size_t)bt * U_ * J_;

    constexpr int UNITS = U_ * (J_ / 8);       // 3200 8-half units
    for (int idx = threadIdx.x; idx < UNITS; idx += 256) {
        const int u = idx >> 6;                // /(J_/8)=64
        const int j = (idx & 63) * 8;
        const float* dp = dbase + (size_t)u * J_ + j;
        float4 d0 = *reinterpret_cast<const float4*>(dp);
        float4 d1 = *reinterpret_cast<const float4*>(dp + 4);
        float4 e0 = *reinterpret_cast<const float4*>(se + j);
        float4 e1 = *reinterpret_cast<const float4*>(se + j + 4);

        __half2 h0 = __floats2half2_rn(tanh_fast(e0.x + d0.x), tanh_fast(e0.y + d0.y));
        __half2 h1 = __floats2half2_rn(tanh_fast(e0.z + d0.z), tanh_fast(e0.w + d0.w));
        __half2 h2 = __floats2half2_rn(tanh_fast(e1.x + d1.x), tanh_fast(e1.y + d1.y));
        __half2 h3 = __floats2half2_rn(tanh_fast(e1.z + d1.z), tanh_fast(e1.w + d1.w));
        uint4 st;
        st.x = *reinterpret_cast<uint32_t*>(&h0);
        st.y = *reinterpret_cast<uint32_t*>(&h1);
        st.z = *reinterpret_cast<uint32_t*>(&h2);
        st.w = *reinterpret_cast<uint32_t*>(&h3);
        *reinterpret_cast<uint4*>(zbase + (size_t)u * J_ + j) = st;
    }
}

// ---------------------------------------------------------------------------
// Main GEMM on mma.sync fp16 (fp32 accum):
//   out[80000, 1024] = Zh[80000, 512] @ Wh[1024, 512]^T + b_out
// BM=128, BN=256, BK=64 halves; 512 threads (16 warps, 4x4), warp tile 32x64.
// 3-stage cp.async pipeline. Smem rows: 72 halves (144 B) -> conflict-free.
// ---------------------------------------------------------------------------
constexpr int TC_BM = 128;
constexpr int TC_BN = 256;
constexpr int TC_BK = 64;              // halves per K-block (128 B rows)
constexpr int TC_NKB = J_ / TC_BK;     // 8 K-blocks
constexpr int TC_THREADS = 512;
constexpr int TC_STAGES = 3;

constexpr int ROWH = 72;               // halves per smem row (64 + 8 pad)
constexpr int ROWB = ROWH * 2;         // 144 bytes
constexpr int A_BYTES = TC_BM * ROWB;            // 18432
constexpr int B_BYTES = TC_BN * ROWB;            // 36864
constexpr int STAGE_BYTES = A_BYTES + B_BYTES;   // 55296
constexpr int SM_BIAS  = TC_STAGES * STAGE_BYTES;       // 165888
constexpr int SM_TOTAL = SM_BIAS + TC_BN * 4;           // 166912

__global__ __launch_bounds__(TC_THREADS, 1)
void joint_out_mma(const __half* __restrict__ Z,
                   const __half* __restrict__ Wh,
                   const float* __restrict__ bias,
                   float* __restrict__ out)
{
    extern __shared__ char smem[];
    const uint32_t smem_base = smem_to_u32(smem);

    const int tid  = threadIdx.x;
    const int lane = tid & 31;
    const int wid  = tid >> 5;
    const int wm   = wid & 3;        // warp row (M)
    const int wn   = wid >> 2;       // warp col (N)

    const int brow = blockIdx.y * TC_BM;
    const int bcol = blockIdx.x * TC_BN;

    const __half* Abase = Z  + (size_t)brow * J_;
    const __half* Bbase = Wh + (size_t)bcol * J_;

    // stage bias
    float* sb = reinterpret_cast<float*>(smem + SM_BIAS);
    if (tid < TC_BN) sb[tid] = bias[bcol + tid];

    // --- loader: 16B granules (8 halves), 8 granules per 128B row ---
    auto load_stage = [&](int kt, int s) {
        const uint32_t sba = smem_base + s * STAGE_BYTES;
        const __half* ag = Abase + kt * TC_BK;
        #pragma unroll
        for (int i = 0; i < 2; ++i) {              // A: 128 rows * 8 = 1024 granules
            int g = tid + i * TC_THREADS;
            int row = g >> 3, gc = g & 7;
            CP_ASYNC16(sba + row * ROWB + gc * 16,
                       ag + (size_t)row * J_ + gc * 8);
        }
        const uint32_t sbb = sba + A_BYTES;
        const __half* bg = Bbase + kt * TC_BK;
        #pragma unroll
        for (int i = 0; i < 4; ++i) {              // B: 256 rows * 8 = 2048 granules
            int g = tid + i * TC_THREADS;
            int row = g >> 3, gc = g & 7;
            CP_ASYNC16(sbb + row * ROWB + gc * 16,
                       bg + (size_t)row * J_ + gc * 8);
        }
        CP_ASYNC_COMMIT();
    };

    float acc[2][8][4];
    #pragma unroll
    for (int i = 0; i < 2; ++i)
        #pragma unroll
        for (int j = 0; j < 8; ++j)
            #pragma unroll
            for (int r = 0; r < 4; ++r) acc[i][j][r] = 0.0f;

    load_stage(0, 0);
    load_stage(1, 1);

    const int mA = wm * 32 + (lane >> 2);   // A row base (add i*16, +8)
    const int nB = wn * 64 + (lane >> 2);   // B row base (add j*8)
    const int kq = lane & 3;

    int s = 0;   // stage index kt % 3
    #pragma unroll 1
    for (int kt = 0; kt < TC_NKB; ++kt) {
        // stage kt must be complete; up to one later stage may remain in flight
        if (kt + 1 < TC_NKB)
            asm volatile("cp.async.wait_group 1;" ::: "memory");
        else
            asm volatile("cp.async.wait_group 0;" ::: "memory");
        __syncthreads();   // all warps see stage kt; all done reading buffer (kt+2)%3

        if (kt + 2 < TC_NKB) {
            int s2 = s + 2; if (s2 >= TC_STAGES) s2 -= TC_STAGES;
            load_stage(kt + 2, s2);
        }

        const __half* As = reinterpret_cast<const __half*>(smem + s * STAGE_BYTES);
        const __half* Bs = reinterpret_cast<const __half*>(smem + s * STAGE_BYTES + A_BYTES);

        #pragma unroll
        for (int ks = 0; ks < 4; ++ks) {           // 4 x k16 slices
            const int kb = ks * 16 + 2 * kq;
            uint32_t a[2][4];
            #pragma unroll
            for (int i = 0; i < 2; ++i) {
                const __half* ap = As + (size_t)(mA + i * 16) * ROWH + kb;
                a[i][0] = *reinterpret_cast<const uint32_t*>(ap);
                a[i][1] = *reinterpret_cast<const uint32_t*>(ap + 8 * ROWH);
                a[i][2] = *reinterpret_cast<const uint32_t*>(ap + 8);
                a[i][3] = *reinterpret_cast<const uint32_t*>(ap + 8 * ROWH + 8);
            }
            uint32_t b[8][2];
            #pragma unroll
            for (int j = 0; j < 8; ++j) {
                const __half* bp = Bs + (size_t)(nB + j * 8) * ROWH + kb;
                b[j][0] = *reinterpret_cast<const uint32_t*>(bp);
                b[j][1] = *reinterpret_cast<const uint32_t*>(bp + 8);
            }
            #pragma unroll
            for (int i = 0; i < 2; ++i)
                #pragma unroll
                for (int j = 0; j < 8; ++j)
                    mma_f16(acc[i][j], a[i][0], a[i][1], a[i][2], a[i][3],
                            b[j][0], b[j][1]);
        }

        if (++s >= TC_STAGES) s = 0;
    }

    // --- epilogue: bias + direct global stores ---
    #pragma unroll
    for (int i = 0; i < 2; ++i) {
        const int r = brow + wm * 32 + i * 16 + (lane >> 2);
        #pragma unroll
        for (int j = 0; j < 8; ++j) {
            const int cl = wn * 64 + j * 8 + 2 * (lane & 3);
            const float bx = sb[cl], by = sb[cl + 1];
            float2 v0 = { acc[i][j][0] + bx, acc[i][j][1] + by };
            float2 v1 = { acc[i][j][2] + bx, acc[i][j][3] + by };
            *reinterpret_cast<float2*>(out + (size_t)r * V_ + bcol + cl) = v0;
            *reinterpret_cast<float2*>(out + (size_t)(r + 8) * V_ + bcol + cl) = v1;
        }
    }
}

// ---------------------------------------------------------------------------
extern "C" void kernel_launch(void* const* d_in, const int* in_sizes, int n_in,
                              void* d_out, int out_size)
{
    const float* h_enc = (const float*)d_in[0];   // (1600, 512)
    const float* h_dec = (const float*)d_in[1];   // (400, 512)
    const float* W_enc = (const float*)d_in[2];   // (512, 512)
    const float* b_enc = (const float*)d_in[3];   // (512,)
    const float* W_dec = (const float*)d_in[4];   // (512, 512)
    const float* W_out = (const float*)d_in[5];   // (1024, 512)
    const float* b_out = (const float*)d_in[6];   // (1024,)
    float* out = (float*)d_out;                   // (80000, 1024)

    __half* Zh; cudaGetSymbolAddress((void**)&Zh, g_Zh);
    __half* Wh; cudaGetSymbolAddress((void**)&Wh, g_Wh);

    static bool attr_set = false;
    if (!attr_set) {
        cudaFuncSetAttribute(joint_out_mma,
                             cudaFuncAttributeMaxDynamicSharedMemorySize, SM_TOTAL);
        attr_set = true;
    }

    // 1) fused prep: E gemm, D gemm, W_out->fp16
    {
        dim3 grid(J_ / 64, (ME + 63) / 64, 3);   // (8, 25, 3)
        prep_kernel<<<grid, 256>>>(h_enc, W_enc, b_enc, h_dec, W_dec, W_out);
    }
    // 2) Zh = fp16(tanh_approx(E + D))
    {
        tanh_broadcast_kernel<<<ME, 256>>>();
    }
    // 3) out = Zh @ Wh^T + b_out  on mma.sync fp16
    {
        dim3 grid(V_ / TC_BN, MZ / TC_BM);   // (4, 625)
        joint_out_mma<<<grid, TC_THREADS, SM_TOTAL>>>(Zh, Wh, b_out, out);
    }
}